// round 2
// baseline (speedup 1.0000x reference)
#include <cuda_runtime.h>

// SCVC: out[n, g*OG+o, p, q] = C[g,o]*x[n,g,p]*y[n,g,q] + a[n,g,o,p] + b[n,g,o,q]
//   a[p] = wA0*x[p-1] + wA1*x[p+1]  (zero boundary)
//   b[q] = wB0*y[q-1] + wB1*y[q+1]  (zero boundary)
// Shapes: N=8, G=8, OG=16, DX=DY=256. Output = 256 MiB fp32 -> store-bound.

#define N_  8
#define G_  8
#define OG_ 16
#define DX_ 256
#define DY_ 256
#define PT  16   // p-rows per block

__global__ __launch_bounds__(256) void scvc_kernel(
    const float* __restrict__ x,   // (N, G, DX)
    const float* __restrict__ y,   // (N, G, DY)
    const float* __restrict__ C,   // (G, OG)
    const float* __restrict__ wA,  // (G, OG, 2)
    const float* __restrict__ wB,  // (G, OG, 2)
    float* __restrict__ out)       // (N, G*OG, DX, DY)
{
    __shared__ float sy[DY_];
    __shared__ float sb[DY_];

    const int b  = blockIdx.x;
    const int pt = b & 15;            // DX_/PT = 16 tiles
    const int o  = (b >> 4) & 15;     // OG_ = 16
    const int g  = (b >> 8) & 7;      // G_  = 8
    const int n  = b >> 11;           // N_  = 8

    const int tid = threadIdx.x;
    const int ng = n * G_ + g;
    const int go = g * OG_ + o;

    const float* __restrict__ yrow = y + ng * DY_;
    const float* __restrict__ xrow = x + ng * DX_;

    const float wB0 = wB[go * 2 + 0];
    const float wB1 = wB[go * 2 + 1];
    const float wA0 = wA[go * 2 + 0];
    const float wA1 = wA[go * 2 + 1];
    const float Cgo = C[go];

    // Stage y row; compute b[q] once per block.
    sy[tid] = yrow[tid];
    __syncthreads();
    {
        const float yl = (tid > 0)       ? sy[tid - 1] : 0.0f;
        const float yr = (tid < DY_ - 1) ? sy[tid + 1] : 0.0f;
        sb[tid] = wB0 * yl + wB1 * yr;
    }
    __syncthreads();

    // Thread layout: r = row-within-4, c = float4 column (64 per row).
    const int r = tid >> 6;
    const int c = tid & 63;

    const float4 yv = reinterpret_cast<const float4*>(sy)[c];
    const float4 bv = reinterpret_cast<const float4*>(sb)[c];

    float* __restrict__ obase =
        out + ((size_t)ng * OG_ + o) * (size_t)(DX_ * DY_);

    #pragma unroll
    for (int it = 0; it < PT / 4; ++it) {
        const int p = pt * PT + it * 4 + r;
        const float xp  = xrow[p];
        const float xl  = (p > 0)        ? xrow[p - 1] : 0.0f;
        const float xr2 = (p < DX_ - 1)  ? xrow[p + 1] : 0.0f;
        const float ap  = wA0 * xl + wA1 * xr2;
        const float s   = Cgo * xp;

        float4 v;
        v.x = fmaf(s, yv.x, ap + bv.x);
        v.y = fmaf(s, yv.y, ap + bv.y);
        v.z = fmaf(s, yv.z, ap + bv.z);
        v.w = fmaf(s, yv.w, ap + bv.w);

        // Streaming store: write-once output, bypass L2 persistence.
        __stcs(reinterpret_cast<float4*>(obase + (size_t)p * DY_) + c, v);
    }
}

extern "C" void kernel_launch(void* const* d_in, const int* in_sizes, int n_in,
                              void* d_out, int out_size)
{
    const float* x  = (const float*)d_in[0];
    const float* y  = (const float*)d_in[1];
    const float* C  = (const float*)d_in[2];
    const float* wA = (const float*)d_in[3];
    const float* wB = (const float*)d_in[4];
    float* out = (float*)d_out;

    const int nblocks = N_ * G_ * OG_ * (DX_ / PT);  // 16384
    scvc_kernel<<<nblocks, 256>>>(x, y, C, wA, wB, out);
}